// round 4
// baseline (speedup 1.0000x reference)
#include <cuda_runtime.h>
#include <math.h>

#define HH 496
#define WW 496
#define HW (HH * WW)
#define BDIM 4
#define NTOT (BDIM * HW)
#define TPB 256
#define BLK_PER_B (HW / TPB)         // 246016/256 = 961 exactly
#define NBLK (BDIM * BLK_PER_B)      // 3844
#define NW (TPB / 32)

__device__ float g_num = 0.0f;
__device__ int g_cnt = 0;
__device__ unsigned int g_done = 0;

// Liang-Barsky interval update for one halfplane.
// D(t) = dc + t*(dn-dc); inside = D >= 0.
__device__ __forceinline__ void upd(float dc, float dn, float& t0, float& t1) {
    float den = dc - dn;
    float t = __fdividef(dc, den);
    if (den < 0.0f)      t0 = fmaxf(t0, t);   // D increasing -> lower bound
    else if (den > 0.0f) t1 = fminf(t1, t);   // D decreasing -> upper bound
    else if (dc < 0.0f)  t1 = -1e30f;         // parallel & outside -> empty
}

__global__ void __launch_bounds__(TPB) iou_k(const float* __restrict__ iou_pred,
                                             const int* __restrict__ mask,
                                             const float* __restrict__ box_pred,
                                             const float* __restrict__ box_gt,
                                             float* __restrict__ out) {
    __shared__ float s_red[NW];
    __shared__ int s_cnt[NW];

    const int tid = threadIdx.x;
    const int lane = tid & 31;
    const int w = tid >> 5;
    const int b = blockIdx.x / BLK_PER_B;     // each block lies in one batch slice
    const int n = blockIdx.x * TPB + tid;
    const int hw = n - b * HW;

    // ---- issue EVERYTHING up front: no barriers, maximal MLP ----
    const int m = __ldg(mask + n);
    const float ip = __ldg(iou_pred + n);

    const float* bp = box_pred + (size_t)b * 7 * HW + hw;   // [B,7,H,W] (coalesced)
    const float pa0 = __ldg(bp);
    const float pa1 = __ldg(bp + HW);
    const float pa2 = __ldg(bp + 2 * HW);
    const float pa3 = __ldg(bp + 3 * HW);
    const float pa4 = __ldg(bp + 4 * HW);
    const float pa5 = __ldg(bp + 5 * HW);
    const float pa6 = __ldg(bp + 6 * HW);

    const float* bg = box_gt + (size_t)n * 7;               // [B,H,W,7]
    const float pb0 = __ldg(bg);
    const float pb1 = __ldg(bg + 1);
    const float pb2 = __ldg(bg + 2);
    const float pb3 = __ldg(bg + 3);
    const float pb4 = __ldg(bg + 4);
    const float pb5 = __ldg(bg + 5);
    const float pb6 = __ldg(bg + 6);

    // Start the MUFU chains as soon as headings arrive.
    float sa, ca, sr, cr;
    __sincosf(pa6, &sa, &ca);
    __sincosf(pb6 - pa6, &sr, &cr);

    // Work in box A's frame: rotate world by -heading_a, center at A.
    const float tx = pb0 - pa0, ty = pb1 - pa1;
    const float rx = fmaf(ca, tx, sa * ty);
    const float ry = fmaf(ca, ty, -sa * tx);

    const float hx = 0.5f * pa3, hy = 0.5f * pa4;
    const float lx = 0.5f * pb3, ly = 0.5f * pb4;

    // B corners (CCW); A corners are (+-hx, +-hy) implicitly.
    const float SX[4] = {1.f, -1.f, -1.f, 1.f};
    const float SY[4] = {1.f, 1.f, -1.f, -1.f};
    float bxx[4], byy[4];
#pragma unroll
    for (int i = 0; i < 4; i++) {
        float px_ = SX[i] * lx, py_ = SY[i] * ly;
        bxx[i] = rx + cr * px_ - sr * py_;
        byy[i] = ry + sr * px_ + cr * py_;
    }

    // DB[i][j]: B vertex i vs A halfplane j (A axis-aligned -> trivial adds).
    float DB[4][4];
#pragma unroll
    for (int i = 0; i < 4; i++) {
        DB[i][0] = hy - byy[i];
        DB[i][1] = bxx[i] + hx;
        DB[i][2] = byy[i] + hy;
        DB[i][3] = hx - bxx[i];
    }

    // DA[i][j]: A vertex i vs B halfplane j. k_j doubles as B-edge shoelace cross.
    float DA[4][4], ke[4];
#pragma unroll
    for (int j = 0; j < 4; j++) {
        int j1 = (j + 1) & 3;
        float ex = bxx[j1] - bxx[j];
        float ey = byy[j1] - byy[j];
        float k = fmaf(ey, bxx[j], -ex * byy[j]);
        ke[j] = k;
        float exhy = ex * hy, eyhx = ey * hx;
        float kp = k + exhy, km = k - exhy;
        DA[0][j] = kp - eyhx;
        DA[1][j] = kp + eyhx;
        DA[2][j] = km + eyhx;
        DA[3][j] = km - eyhx;
    }

    // Pass A: A edges clipped by B halfplanes; each cross-term = 2*hx*hy.
    float dtsum = 0.0f;
#pragma unroll
    for (int i = 0; i < 4; i++) {
        int i1 = (i + 1) & 3;
        float t0 = 0.0f, t1 = 1.0f;
#pragma unroll
        for (int j = 0; j < 4; j++) upd(DA[i][j], DA[i1][j], t0, t1);
        dtsum += fmaxf(t1 - t0, 0.0f);
    }
    float acc = dtsum * (2.0f * hx * hy);

    // Pass B: B edges clipped by A halfplanes; cross-term = ke[j].
#pragma unroll
    for (int j = 0; j < 4; j++) {
        int j1 = (j + 1) & 3;
        float t0 = 0.0f, t1 = 1.0f;
#pragma unroll
        for (int i = 0; i < 4; i++) upd(DB[j][i], DB[j1][i], t0, t1);
        acc = fmaf(fmaxf(t1 - t0, 0.0f), ke[j], acc);
    }

    const float inter_bev = 0.5f * fabsf(acc);

    const float za0 = pa2 - 0.5f * pa5, za1 = pa2 + 0.5f * pa5;
    const float zb0 = pb2 - 0.5f * pb5, zb1 = pb2 + 0.5f * pb5;
    const float zo = fmaxf(fminf(za1, zb1) - fmaxf(za0, zb0), 0.0f);

    const float inter_vol = inter_bev * zo;
    const float vol_a = pa3 * pa4 * pa5;
    const float vol_b = pb3 * pb4 * pb5;
    const float iou = inter_vol / (vol_a + vol_b - inter_vol + 1e-7f);

    float lnum = (m != 0) ? fabsf(ip - (2.0f * iou - 1.0f)) : 0.0f;
    int lcnt = __popc(__ballot_sync(0xffffffffu, m != 0));   // per-warp exact count

    // ---- block reduction ----
#pragma unroll
    for (int off = 16; off > 0; off >>= 1)
        lnum += __shfl_down_sync(0xffffffffu, lnum, off);
    if (lane == 0) { s_red[w] = lnum; s_cnt[w] = lcnt; }
    __syncthreads();
    if (w == 0) {
        lnum = (lane < NW) ? s_red[lane] : 0.0f;
        lcnt = (lane < NW) ? s_cnt[lane] : 0;
#pragma unroll
        for (int off = NW / 2; off > 0; off >>= 1) {
            lnum += __shfl_down_sync(0xffffffffu, lnum, off);
            lcnt += __shfl_down_sync(0xffffffffu, lcnt, off);
        }
        // ---- last-block finalize (threadfence reduction pattern) ----
        if (lane == 0) {
            atomicAdd(&g_num, lnum);
            atomicAdd(&g_cnt, lcnt);
            __threadfence();
            unsigned int old = atomicAdd(&g_done, 1u);
            if (old == NBLK - 1) {
                __threadfence();
                float num = *((volatile float*)&g_num);
                int cnt = *((volatile int*)&g_cnt);
                out[0] = num / ((float)cnt + 1e-4f);
                g_num = 0.0f;       // reset for next graph replay
                g_cnt = 0;
                g_done = 0u;
            }
        }
    }
}

extern "C" void kernel_launch(void* const* d_in, const int* in_sizes, int n_in,
                              void* d_out, int out_size) {
    const float* iou_pred = (const float*)d_in[0];
    const int* mask = (const int*)d_in[1];
    // d_in[2] = ind (unused)
    const float* box_pred = (const float*)d_in[3];
    const float* box_gt = (const float*)d_in[4];
    float* out = (float*)d_out;

    iou_k<<<NBLK, TPB>>>(iou_pred, mask, box_pred, box_gt, out);
}

// round 5
// speedup vs baseline: 1.1416x; 1.1416x over previous
#include <cuda_runtime.h>
#include <math.h>

#define HH 496
#define WW 496
#define HW (HH * WW)
#define BDIM 4
#define NTOT (BDIM * HW)
#define TPB 256
#define BLK_PER_B (HW / TPB)         // 246016/256 = 961 exactly
#define NBLK (BDIM * BLK_PER_B)      // 3844
#define NW (TPB / 32)

__device__ float g_num = 0.0f;
__device__ int g_cnt = 0;
__device__ unsigned int g_done = 0;

// Liang-Barsky interval update for one halfplane.
// D(t) = dc + t*(dn-dc); inside = D >= 0.
__device__ __forceinline__ void upd(float dc, float dn, float& t0, float& t1) {
    float den = dc - dn;
    float t = __fdividef(dc, den);
    if (den < 0.0f)      t0 = fmaxf(t0, t);   // D increasing -> lower bound
    else if (den > 0.0f) t1 = fminf(t1, t);   // D decreasing -> upper bound
    else if (dc < 0.0f)  t1 = -1e30f;         // parallel & outside -> empty
}

__global__ void __launch_bounds__(TPB, 5) iou_k(const float* __restrict__ iou_pred,
                                                const int* __restrict__ mask,
                                                const float* __restrict__ box_pred,
                                                const float* __restrict__ box_gt,
                                                float* __restrict__ out) {
    __shared__ float s_red[NW];
    __shared__ int s_cnt[NW];

    const int tid = threadIdx.x;
    const int lane = tid & 31;
    const int w = tid >> 5;
    const int b = blockIdx.x / BLK_PER_B;
    const int n = blockIdx.x * TPB + tid;
    const int hw = n - b * HW;

    // ---- issue all loads up front: no barriers, maximal MLP ----
    const int m = __ldg(mask + n);
    const float ip = __ldg(iou_pred + n);

    const float* bp = box_pred + (size_t)b * 7 * HW + hw;   // [B,7,H,W] (coalesced)
    const float pa0 = __ldg(bp);
    const float pa1 = __ldg(bp + HW);
    const float pa2 = __ldg(bp + 2 * HW);
    const float pa3 = __ldg(bp + 3 * HW);
    const float pa4 = __ldg(bp + 4 * HW);
    const float pa5 = __ldg(bp + 5 * HW);
    const float pa6 = __ldg(bp + 6 * HW);

    const float* bg = box_gt + (size_t)n * 7;               // [B,H,W,7]
    const float pb0 = __ldg(bg);
    const float pb1 = __ldg(bg + 1);
    const float pb2 = __ldg(bg + 2);
    const float pb3 = __ldg(bg + 3);
    const float pb4 = __ldg(bg + 4);
    const float pb5 = __ldg(bg + 5);
    const float pb6 = __ldg(bg + 6);

    // Fold z/volume terms immediately so pa2/pa5/pb2/pb5 die early.
    const float vol_a = pa3 * pa4 * pa5;
    const float vol_b = pb3 * pb4 * pb5;
    const float zo = fmaxf(fminf(pa2 + 0.5f * pa5, pb2 + 0.5f * pb5) -
                           fmaxf(pa2 - 0.5f * pa5, pb2 - 0.5f * pb5), 0.0f);

    // Start MUFU chains early.
    float sa, ca, sr, cr;
    __sincosf(pa6, &sa, &ca);
    __sincosf(pb6 - pa6, &sr, &cr);

    // Box A's frame: rotate world by -heading_a, center at A.
    const float tx = pb0 - pa0, ty = pb1 - pa1;
    const float rx = fmaf(ca, tx, sa * ty);
    const float ry = fmaf(ca, ty, -sa * tx);

    const float hx = 0.5f * pa3, hy = 0.5f * pa4;
    const float lx = 0.5f * pb3, ly = 0.5f * pb4;

    // B corners (CCW); A corners are (+-hx, +-hy) implicit.
    const float SX[4] = {1.f, -1.f, -1.f, 1.f};
    const float SY[4] = {1.f, 1.f, -1.f, -1.f};
    float bxx[4], byy[4];
#pragma unroll
    for (int i = 0; i < 4; i++) {
        float px_ = SX[i] * lx, py_ = SY[i] * ly;
        bxx[i] = rx + cr * px_ - sr * py_;
        byy[i] = ry + sr * px_ + cr * py_;
    }

    // Per-B-halfplane reduced coefficients (no DA/DB arrays):
    // D(A-corner s) = {kp or km} ± eyhx, with kp = k+ex*hy, km = k-ex*hy.
    float kp[4], km[4], eyhx[4], ke[4];
#pragma unroll
    for (int j = 0; j < 4; j++) {
        int j1 = (j + 1) & 3;
        float ex = bxx[j1] - bxx[j];
        float ey = byy[j1] - byy[j];
        float k = fmaf(ey, bxx[j], -ex * byy[j]);
        ke[j] = k;                      // doubles as B-edge shoelace cross
        float exhy = ex * hy;
        kp[j] = k + exhy;
        km[j] = k - exhy;
        eyhx[j] = ey * hx;
    }

    // A-corner j-th halfplane distance, vertex index 0..3 ((+,+),(-,+),(-,-),(+,-)).
    auto dA = [&](int v, int j) -> float {
        float base = (v == 0 || v == 1) ? kp[j] : km[j];
        float sgn = (v == 1 || v == 2) ? eyhx[j] : -eyhx[j];
        return base + sgn;
    };

    // Pass A: A edges clipped by B halfplanes; each cross-term = 2*hx*hy.
    float dtsum = 0.0f;
#pragma unroll
    for (int i = 0; i < 4; i++) {
        const int i1 = (i + 1) & 3;
        float t0 = 0.0f, t1 = 1.0f;
#pragma unroll
        for (int j = 0; j < 4; j++) upd(dA(i, j), dA(i1, j), t0, t1);
        dtsum += fmaxf(t1 - t0, 0.0f);
    }
    float acc = dtsum * (2.0f * hx * hy);

    // Pass B: B edges clipped by A halfplanes (distances on the fly);
    // cross-term = ke[j].
#pragma unroll
    for (int j = 0; j < 4; j++) {
        const int j1 = (j + 1) & 3;
        float t0 = 0.0f, t1 = 1.0f;
        upd(hy - byy[j], hy - byy[j1], t0, t1);
        upd(bxx[j] + hx, bxx[j1] + hx, t0, t1);
        upd(byy[j] + hy, byy[j1] + hy, t0, t1);
        upd(hx - bxx[j], hx - bxx[j1], t0, t1);
        acc = fmaf(fmaxf(t1 - t0, 0.0f), ke[j], acc);
    }

    const float inter_vol = 0.5f * fabsf(acc) * zo;
    const float iou = inter_vol / (vol_a + vol_b - inter_vol + 1e-7f);

    float lnum = (m != 0) ? fabsf(ip - (2.0f * iou - 1.0f)) : 0.0f;
    int lcnt = __popc(__ballot_sync(0xffffffffu, m != 0));

    // ---- block reduction ----
#pragma unroll
    for (int off = 16; off > 0; off >>= 1)
        lnum += __shfl_down_sync(0xffffffffu, lnum, off);
    if (lane == 0) { s_red[w] = lnum; s_cnt[w] = lcnt; }
    __syncthreads();
    if (w == 0) {
        lnum = (lane < NW) ? s_red[lane] : 0.0f;
        lcnt = (lane < NW) ? s_cnt[lane] : 0;
#pragma unroll
        for (int off = NW / 2; off > 0; off >>= 1) {
            lnum += __shfl_down_sync(0xffffffffu, lnum, off);
            lcnt += __shfl_down_sync(0xffffffffu, lcnt, off);
        }
        // ---- last-block finalize (threadfence reduction pattern) ----
        if (lane == 0) {
            atomicAdd(&g_num, lnum);
            atomicAdd(&g_cnt, lcnt);
            __threadfence();
            unsigned int old = atomicAdd(&g_done, 1u);
            if (old == NBLK - 1) {
                __threadfence();
                float num = *((volatile float*)&g_num);
                int cnt = *((volatile int*)&g_cnt);
                out[0] = num / ((float)cnt + 1e-4f);
                g_num = 0.0f;       // reset for next graph replay
                g_cnt = 0;
                g_done = 0u;
            }
        }
    }
}

extern "C" void kernel_launch(void* const* d_in, const int* in_sizes, int n_in,
                              void* d_out, int out_size) {
    const float* iou_pred = (const float*)d_in[0];
    const int* mask = (const int*)d_in[1];
    // d_in[2] = ind (unused)
    const float* box_pred = (const float*)d_in[3];
    const float* box_gt = (const float*)d_in[4];
    float* out = (float*)d_out;

    iou_k<<<NBLK, TPB>>>(iou_pred, mask, box_pred, box_gt, out);
}